// round 4
// baseline (speedup 1.0000x reference)
#include <cuda_runtime.h>
#include <math.h>
#include <stdint.h>

// Problem dims (fixed)
constexpr int CB   = 2;
constexpr int CL   = 1024;
constexpr int CD   = 1024;
constexpr int CDIN = 2048;
constexpr int CN   = 16;
constexpr int CR   = 64;
constexpr int CK   = 4;
constexpr int CML  = CB * CL;      // 2048
constexpr int CXD  = CR + 2 * CN;  // 96
constexpr float CLN_EPS = 1e-5f;

// ---------------- scratch (device globals; no allocation) ----------------
__device__ float g_xz   [CML * (2*CDIN)];
__device__ float g_xc   [CML * CDIN];
__device__ float g_xdbl [CML * CXD];
__device__ float g_delta[CML * CDIN];
__device__ float g_pre  [CML * CD];
// tf32 hi/lo split operands
__device__ float g_x_h   [CML * CD],     g_x_l   [CML * CD];
__device__ float g_Win_h [CD * 2*CDIN],  g_Win_l [CD * 2*CDIN];
__device__ float g_Wx_h  [CDIN * CXD],   g_Wx_l  [CDIN * CXD];
__device__ float g_Wdt_h [CR * CDIN],    g_Wdt_l [CR * CDIN];
__device__ float g_Wout_h[CDIN * CD],    g_Wout_l[CDIN * CD];
__device__ float g_xc_h  [CML * CDIN],   g_xc_l  [CML * CDIN];
__device__ float g_xdbl_h[CML * CXD],    g_xdbl_l[CML * CXD];
__device__ float g_yg_h  [CML * CDIN],   g_yg_l  [CML * CDIN];

// ---------------- helpers ----------------
__device__ __forceinline__ void split_tf32(float x, uint32_t& hi, uint32_t& lo)
{
    uint32_t h;
    asm("cvt.rna.tf32.f32 %0, %1;" : "=r"(h) : "f"(x));
    float hf = __uint_as_float(h);
    float lf = x - hf;
    uint32_t l;
    asm("cvt.rna.tf32.f32 %0, %1;" : "=r"(l) : "f"(lf));
    hi = h; lo = l;
}

__device__ __forceinline__ void mma_tf32(float* acc, const uint32_t* a, const uint32_t* b)
{
    asm volatile(
        "mma.sync.aligned.m16n8k8.row.col.f32.tf32.tf32.f32 "
        "{%0,%1,%2,%3}, {%4,%5,%6,%7}, {%8,%9}, {%0,%1,%2,%3};\n"
        : "+f"(acc[0]), "+f"(acc[1]), "+f"(acc[2]), "+f"(acc[3])
        : "r"(a[0]), "r"(a[1]), "r"(a[2]), "r"(a[3]), "r"(b[0]), "r"(b[1]));
}

__device__ __forceinline__ void cp_async16(void* smem_ptr, const void* gptr)
{
    uint32_t s = (uint32_t)__cvta_generic_to_shared(smem_ptr);
    asm volatile("cp.async.cg.shared.global [%0], [%1], 16;\n" :: "r"(s), "l"(gptr));
}

// ---------------- split-precompute kernel (x + all weights) ----------------
__global__ void split_all_kernel(const float* __restrict__ x,
                                 const float* __restrict__ Win,
                                 const float* __restrict__ Wx,
                                 const float* __restrict__ Wdt,
                                 const float* __restrict__ Wout)
{
    const int n0 = CML*CD;
    const int n1 = n0 + CD*2*CDIN;
    const int n2 = n1 + CDIN*CXD;
    const int n3 = n2 + CR*CDIN;
    const int n4 = n3 + CDIN*CD;
    int i = blockIdx.x * blockDim.x + threadIdx.x;
    if (i >= n4) return;
    const float* src; float* dh; float* dl; int off;
    if      (i < n0) { src = x;    dh = g_x_h;    dl = g_x_l;    off = i; }
    else if (i < n1) { src = Win;  dh = g_Win_h;  dl = g_Win_l;  off = i - n0; }
    else if (i < n2) { src = Wx;   dh = g_Wx_h;   dl = g_Wx_l;   off = i - n1; }
    else if (i < n3) { src = Wdt;  dh = g_Wdt_h;  dl = g_Wdt_l;  off = i - n2; }
    else             { src = Wout; dh = g_Wout_h; dl = g_Wout_l; off = i - n3; }
    uint32_t h, l;
    split_tf32(src[off], h, l);
    dh[off] = __uint_as_float(h);
    dl[off] = __uint_as_float(l);
}

// ---------------- TF32-split tensor-core GEMM v2 ----------------
// Operands pre-split (hi/lo fp32 arrays). cp.async double-buffered.
// BM=BN=128, BK=16, 256 thr = 8 warps (2x4), warp tile 64x32.
// EPI: 0 plain, 1 softplus(acc+bias[col]), 2 fp32 + hi/lo split stores.
constexpr int BM = 128, BN = 128, BK = 16;
constexpr int AST = BK + 4;     // 20 floats per A row
constexpr int BST = BN + 8;     // 136 floats per B row (conflict-free frags)
constexpr int S_AL = BM * AST;              // 2560
constexpr int S_BH = 2 * BM * AST;          // 5120
constexpr int S_BL = S_BH + BK * BST;       // 7296
constexpr int STAGE_F = S_BL + BK * BST;    // 9472 floats/stage
constexpr int GEMM_SMEM = 2 * STAGE_F * 4;  // 75776 bytes

template<int EPI>
__global__ __launch_bounds__(256)
void tgemm2(int M, int N, int K,
            const float* __restrict__ Ah_g, const float* __restrict__ Al_g, int lda,
            const float* __restrict__ Bh_g, const float* __restrict__ Bl_g, int ldb,
            float* __restrict__ C, float* __restrict__ Ch, float* __restrict__ Cl,
            int ldc, const float* __restrict__ bias)
{
    extern __shared__ float sm[];

    const int tid  = threadIdx.x;
    const int warp = tid >> 5;
    const int lane = tid & 31;
    const int g    = lane >> 2;
    const int tg   = lane & 3;

    const int row0 = blockIdx.y * BM;
    const int col0 = blockIdx.x * BN;
    const int wm0  = (warp >> 2) * 64;
    const int wn0  = (warp & 3) * 32;

    const int aRow = tid >> 1;
    const int aCol = (tid & 1) * 8;
    const int bRow = tid >> 4;
    const int bCol = (tid & 15) * 8;

    float acc[4][4][4];
    #pragma unroll
    for (int i = 0; i < 4; i++)
        #pragma unroll
        for (int j = 0; j < 4; j++)
            #pragma unroll
            for (int r = 0; r < 4; r++) acc[i][j][r] = 0.f;

    const int gcolB   = col0 + bCol;
    const bool bIn    = (gcolB + 8 <= N);

    // stage loader
    auto load_stage = [&](int stg, int k0) {
        float* Ah = sm + stg * STAGE_F;
        float* Al = Ah + S_AL;
        float* Bh = sm + stg * STAGE_F + S_BH;
        float* Bl = sm + stg * STAGE_F + S_BL;

        const size_t aoff = (size_t)(row0 + aRow) * lda + (k0 + aCol);
        cp_async16(&Ah[aRow * AST + aCol    ], Ah_g + aoff);
        cp_async16(&Ah[aRow * AST + aCol + 4], Ah_g + aoff + 4);
        cp_async16(&Al[aRow * AST + aCol    ], Al_g + aoff);
        cp_async16(&Al[aRow * AST + aCol + 4], Al_g + aoff + 4);

        if (bIn) {
            const size_t boff = (size_t)(k0 + bRow) * ldb + gcolB;
            cp_async16(&Bh[bRow * BST + bCol    ], Bh_g + boff);
            cp_async16(&Bh[bRow * BST + bCol + 4], Bh_g + boff + 4);
            cp_async16(&Bl[bRow * BST + bCol    ], Bl_g + boff);
            cp_async16(&Bl[bRow * BST + bCol + 4], Bl_g + boff + 4);
        } else {
            #pragma unroll
            for (int j = 0; j < 8; j++) {
                Bh[bRow * BST + bCol + j] = 0.f;
                Bl[bRow * BST + bCol + j] = 0.f;
            }
        }
    };

    const int ntiles = K / BK;
    load_stage(0, 0);
    asm volatile("cp.async.commit_group;\n" ::: "memory");

    int stg = 0;
    for (int kt = 0; kt < ntiles; kt++) {
        if (kt + 1 < ntiles) {
            load_stage(stg ^ 1, (kt + 1) * BK);
            asm volatile("cp.async.commit_group;\n" ::: "memory");
            asm volatile("cp.async.wait_group 1;\n" ::: "memory");
        } else {
            asm volatile("cp.async.wait_group 0;\n" ::: "memory");
        }
        __syncthreads();

        const float* Ah = sm + stg * STAGE_F;
        const float* Al = Ah + S_AL;
        const float* Bh = sm + stg * STAGE_F + S_BH;
        const float* Bl = sm + stg * STAGE_F + S_BL;

        #pragma unroll
        for (int ks = 0; ks < BK; ks += 8) {
            uint32_t afh[4][4], afl[4][4];
            #pragma unroll
            for (int mt = 0; mt < 4; mt++) {
                int r = wm0 + mt * 16 + g;
                const float* p0h = Ah + (size_t)r * AST + ks + tg;
                const float* p1h = Ah + (size_t)(r + 8) * AST + ks + tg;
                afh[mt][0] = __float_as_uint(p0h[0]);
                afh[mt][1] = __float_as_uint(p1h[0]);
                afh[mt][2] = __float_as_uint(p0h[4]);
                afh[mt][3] = __float_as_uint(p1h[4]);
                const float* p0l = Al + (size_t)r * AST + ks + tg;
                const float* p1l = Al + (size_t)(r + 8) * AST + ks + tg;
                afl[mt][0] = __float_as_uint(p0l[0]);
                afl[mt][1] = __float_as_uint(p1l[0]);
                afl[mt][2] = __float_as_uint(p0l[4]);
                afl[mt][3] = __float_as_uint(p1l[4]);
            }
            uint32_t bfh[4][2], bfl[4][2];
            #pragma unroll
            for (int nt = 0; nt < 4; nt++) {
                int c = wn0 + nt * 8 + g;
                bfh[nt][0] = __float_as_uint(Bh[(ks + tg) * BST + c]);
                bfh[nt][1] = __float_as_uint(Bh[(ks + tg + 4) * BST + c]);
                bfl[nt][0] = __float_as_uint(Bl[(ks + tg) * BST + c]);
                bfl[nt][1] = __float_as_uint(Bl[(ks + tg + 4) * BST + c]);
            }
            #pragma unroll
            for (int mt = 0; mt < 4; mt++)
                #pragma unroll
                for (int nt = 0; nt < 4; nt++) {
                    mma_tf32(acc[mt][nt], afh[mt], bfh[nt]);
                    mma_tf32(acc[mt][nt], afh[mt], bfl[nt]);
                    mma_tf32(acc[mt][nt], afl[mt], bfh[nt]);
                }
        }
        __syncthreads();
        stg ^= 1;
    }

    // ---- store ----
    #pragma unroll
    for (int mt = 0; mt < 4; mt++) {
        int r0 = row0 + wm0 + mt * 16 + g;
        #pragma unroll
        for (int nt = 0; nt < 4; nt++) {
            int c0 = col0 + wn0 + nt * 8 + 2 * tg;
            #pragma unroll
            for (int rr = 0; rr < 2; rr++) {
                int r = r0 + rr * 8;
                #pragma unroll
                for (int cc = 0; cc < 2; cc++) {
                    int c = c0 + cc;
                    if (c < N) {
                        float v = acc[mt][nt][rr * 2 + cc];
                        if (EPI == 1) {
                            v = v + bias[c];
                            v = (v > 20.f) ? v : log1pf(__expf(v));
                        }
                        C[(size_t)r * ldc + c] = v;
                        if (EPI == 2) {
                            uint32_t h, l;
                            split_tf32(v, h, l);
                            Ch[(size_t)r * ldc + c] = __uint_as_float(h);
                            Cl[(size_t)r * ldc + c] = __uint_as_float(l);
                        }
                    }
                }
            }
        }
    }
}

// ---------------- causal depthwise conv (K=4) + SiLU (+ split epi) ----------------
__global__ void conv_silu_kernel(const float* __restrict__ conv_w,
                                 const float* __restrict__ conv_b)
{
    int i = blockIdx.x * blockDim.x + threadIdx.x;
    if (i >= CML * CDIN) return;
    int d  = i & (CDIN - 1);
    int bl = i >> 11;
    int l  = bl & (CL - 1);
    int b  = bl >> 10;

    float acc = conv_b[d];
    #pragma unroll
    for (int k = 0; k < CK; k++) {
        int ll = l - (CK - 1) + k;
        if (ll >= 0) {
            float xin = g_xz[(size_t)(b * CL + ll) * (2 * CDIN) + d];
            acc = fmaf(xin, conv_w[d * CK + k], acc);
        }
    }
    float sig = 1.f / (1.f + __expf(-acc));
    float v = acc * sig;
    g_xc[i] = v;
    uint32_t h, l2;
    split_tf32(v, h, l2);
    g_xc_h[i] = __uint_as_float(h);
    g_xc_l[i] = __uint_as_float(l2);
}

// ---------------- selective scan (+ skip + gate + split epi) ----------------
__global__ __launch_bounds__(128)
void scan_kernel(const float* __restrict__ A_log,
                 const float* __restrict__ D_skip)
{
    int warp = (blockIdx.x * blockDim.x + threadIdx.x) >> 5;
    int lane = threadIdx.x & 31;
    int half = lane >> 4;
    int n    = lane & 15;

    int b = warp >> 10;
    int d = ((warp & 1023) << 1) + half;

    float a_coef = -expf(A_log[d * CN + n]);
    float d_skip = D_skip[d];
    float h = 0.f;

    const size_t bl0 = (size_t)b * CL;
    for (int t = 0; t < CL; t++) {
        size_t bl = bl0 + t;
        float dv = g_delta[bl * CDIN + d];
        float xc = g_xc   [bl * CDIN + d];
        float Bn = g_xdbl [bl * CXD + CR + n];
        float Cn = g_xdbl [bl * CXD + CR + CN + n];

        float dA = __expf(dv * a_coef);
        h = fmaf(dA, h, dv * Bn * xc);

        float v = h * Cn;
        v += __shfl_xor_sync(0xffffffffu, v, 8);
        v += __shfl_xor_sync(0xffffffffu, v, 4);
        v += __shfl_xor_sync(0xffffffffu, v, 2);
        v += __shfl_xor_sync(0xffffffffu, v, 1);

        if (n == 0) {
            float zv = g_xz[bl * (2 * CDIN) + CDIN + d];
            float yv = v + xc * d_skip;
            float sig = 1.f / (1.f + __expf(-zv));
            float yg = yv * (zv * sig);
            uint32_t hh, ll;
            split_tf32(yg, hh, ll);
            g_yg_h[bl * CDIN + d] = __uint_as_float(hh);
            g_yg_l[bl * CDIN + d] = __uint_as_float(ll);
        }
    }
}

// ---------------- LayerNorm over last dim (1024) ----------------
__global__ __launch_bounds__(256)
void ln_kernel(const float* __restrict__ gamma,
               const float* __restrict__ beta,
               float* __restrict__ out)
{
    int row = blockIdx.x;
    const float* p = g_pre + (size_t)row * CD;
    int tid = threadIdx.x;

    float s = 0.f, s2 = 0.f;
    for (int c = tid; c < CD; c += 256) {
        float v = p[c];
        s  += v;
        s2 += v * v;
    }
    #pragma unroll
    for (int o = 16; o >= 1; o >>= 1) {
        s  += __shfl_xor_sync(0xffffffffu, s,  o);
        s2 += __shfl_xor_sync(0xffffffffu, s2, o);
    }
    __shared__ float shs[8], shs2[8];
    int wid = tid >> 5;
    if ((tid & 31) == 0) { shs[wid] = s; shs2[wid] = s2; }
    __syncthreads();
    if (tid < 32) {
        s  = (tid < 8) ? shs[tid]  : 0.f;
        s2 = (tid < 8) ? shs2[tid] : 0.f;
        #pragma unroll
        for (int o = 4; o >= 1; o >>= 1) {
            s  += __shfl_xor_sync(0xffffffffu, s,  o);
            s2 += __shfl_xor_sync(0xffffffffu, s2, o);
        }
        if (tid == 0) { shs[0] = s; shs2[0] = s2; }
    }
    __syncthreads();
    float mean = shs[0] * (1.f / CD);
    float var  = shs2[0] * (1.f / CD) - mean * mean;
    float rstd = rsqrtf(var + CLN_EPS);

    for (int c = tid; c < CD; c += 256) {
        float v = p[c];
        out[(size_t)row * CD + c] = (v - mean) * rstd * gamma[c] + beta[c];
    }
}

// ---------------- launch ----------------
extern "C" void kernel_launch(void* const* d_in, const int* in_sizes, int n_in,
                              void* d_out, int out_size)
{
    const float* x      = (const float*)d_in[0];
    const float* W_in   = (const float*)d_in[1];
    const float* conv_w = (const float*)d_in[2];
    const float* conv_b = (const float*)d_in[3];
    const float* W_x    = (const float*)d_in[4];
    const float* W_dt   = (const float*)d_in[5];
    const float* b_dt   = (const float*)d_in[6];
    const float* A_log  = (const float*)d_in[7];
    const float* D_skip = (const float*)d_in[8];
    const float* W_out  = (const float*)d_in[9];
    const float* ln_g   = (const float*)d_in[10];
    const float* ln_b   = (const float*)d_in[11];
    float* out = (float*)d_out;

    cudaFuncSetAttribute(tgemm2<0>, cudaFuncAttributeMaxDynamicSharedMemorySize, GEMM_SMEM);
    cudaFuncSetAttribute(tgemm2<1>, cudaFuncAttributeMaxDynamicSharedMemorySize, GEMM_SMEM);
    cudaFuncSetAttribute(tgemm2<2>, cudaFuncAttributeMaxDynamicSharedMemorySize, GEMM_SMEM);

    float *p_xz, *p_xdbl, *p_delta, *p_pre;
    float *p_xh, *p_xl, *p_Winh, *p_Winl, *p_Wxh, *p_Wxl, *p_Wdth, *p_Wdtl, *p_Wouth, *p_Woutl;
    float *p_xch, *p_xcl, *p_xdblh, *p_xdbll, *p_ygh, *p_ygl;
    cudaGetSymbolAddress((void**)&p_xz,    g_xz);
    cudaGetSymbolAddress((void**)&p_xdbl,  g_xdbl);
    cudaGetSymbolAddress((void**)&p_delta, g_delta);
    cudaGetSymbolAddress((void**)&p_pre,   g_pre);
    cudaGetSymbolAddress((void**)&p_xh,    g_x_h);
    cudaGetSymbolAddress((void**)&p_xl,    g_x_l);
    cudaGetSymbolAddress((void**)&p_Winh,  g_Win_h);
    cudaGetSymbolAddress((void**)&p_Winl,  g_Win_l);
    cudaGetSymbolAddress((void**)&p_Wxh,   g_Wx_h);
    cudaGetSymbolAddress((void**)&p_Wxl,   g_Wx_l);
    cudaGetSymbolAddress((void**)&p_Wdth,  g_Wdt_h);
    cudaGetSymbolAddress((void**)&p_Wdtl,  g_Wdt_l);
    cudaGetSymbolAddress((void**)&p_Wouth, g_Wout_h);
    cudaGetSymbolAddress((void**)&p_Woutl, g_Wout_l);
    cudaGetSymbolAddress((void**)&p_xch,   g_xc_h);
    cudaGetSymbolAddress((void**)&p_xcl,   g_xc_l);
    cudaGetSymbolAddress((void**)&p_xdblh, g_xdbl_h);
    cudaGetSymbolAddress((void**)&p_xdbll, g_xdbl_l);
    cudaGetSymbolAddress((void**)&p_ygh,   g_yg_h);
    cudaGetSymbolAddress((void**)&p_ygl,   g_yg_l);

    // split x + weights
    {
        int total = CML*CD + CD*2*CDIN + CDIN*CXD + CR*CDIN + CDIN*CD;
        split_all_kernel<<<(total + 255)/256, 256>>>(x, W_in, W_x, W_dt, W_out);
    }

    dim3 thr(256);

    // G1: xz = x @ W_in   [2048,1024]x[1024,4096]
    tgemm2<0><<<dim3((2*CDIN)/128, CML/128), thr, GEMM_SMEM>>>(
        CML, 2*CDIN, CD, p_xh, p_xl, CD, p_Winh, p_Winl, 2*CDIN,
        p_xz, nullptr, nullptr, 2*CDIN, nullptr);

    // conv + silu (+ split)
    conv_silu_kernel<<<(CML*CDIN + 255)/256, 256>>>(conv_w, conv_b);

    // G2: x_dbl = x_conv @ W_x   [2048,2048]x[2048,96]  (+ split epi)
    tgemm2<2><<<dim3(1, CML/128), thr, GEMM_SMEM>>>(
        CML, CXD, CDIN, p_xch, p_xcl, CDIN, p_Wxh, p_Wxl, CXD,
        p_xdbl, p_xdblh, p_xdbll, CXD, nullptr);

    // G3: delta = softplus(dt @ W_dt + b_dt)   [2048,64]x[64,2048]
    tgemm2<1><<<dim3(CDIN/128, CML/128), thr, GEMM_SMEM>>>(
        CML, CDIN, CR, p_xdblh, p_xdbll, CXD, p_Wdth, p_Wdtl, CDIN,
        p_delta, nullptr, nullptr, CDIN, b_dt);

    // scan (+ skip + gate + split)
    scan_kernel<<<(CB*CDIN/2)*32/128, 128>>>(A_log, D_skip);

    // G4: pre = yg @ W_out   [2048,2048]x[2048,1024]
    tgemm2<0><<<dim3(CD/128, CML/128), thr, GEMM_SMEM>>>(
        CML, CD, CDIN, p_ygh, p_ygl, CDIN, p_Wouth, p_Woutl, CD,
        p_pre, nullptr, nullptr, CD, nullptr);

    // LayerNorm
    ln_kernel<<<CML, 256>>>(ln_g, ln_b, out);
}

// round 8
// speedup vs baseline: 1.3439x; 1.3439x over previous
#include <cuda_runtime.h>
#include <cuda_bf16.h>
#include <math.h>
#include <stdint.h>

constexpr int CB   = 2;
constexpr int CL   = 1024;
constexpr int CD   = 1024;
constexpr int CDIN = 2048;
constexpr int CN   = 16;
constexpr int CR   = 64;
constexpr int CK   = 4;
constexpr int CML  = CB * CL;      // 2048
constexpr int CXD  = CR + 2 * CN;  // 96
constexpr int KSPL = 8;            // split-K factor for G2
constexpr float CLN_EPS = 1e-5f;

// ---------------- scratch (device globals; no allocation) ----------------
__device__ float g_xz   [CML * (2*CDIN)];
__device__ float g_xc   [CML * CDIN];
__device__ float g_xdbl [CML * CXD];
__device__ float g_delta[CML * CDIN];
__device__ float g_pre  [CML * CD];
__device__ float g_part [KSPL * CML * CXD];   // split-K partials for G2

// packed bf16x2 hi/lo planes (u32 = two bf16 along K)
__device__ uint32_t g_xp_h  [CML * (CD/2)],     g_xp_l  [CML * (CD/2)];      // x   [2048][512]
__device__ uint32_t g_Winp_h[(2*CDIN) * (CD/2)],g_Winp_l[(2*CDIN) * (CD/2)]; // [4096][512]
__device__ uint32_t g_Wxp_h [CXD * (CDIN/2)],   g_Wxp_l [CXD * (CDIN/2)];    // [96][1024]
__device__ uint32_t g_Wdtp_h[CDIN * (CR/2)],    g_Wdtp_l[CDIN * (CR/2)];     // [2048][32]
__device__ uint32_t g_Woutp_h[CD * (CDIN/2)],   g_Woutp_l[CD * (CDIN/2)];    // [1024][1024]
// activation planes stored as u16 bf16 (reinterpreted as u32 pairs by GEMM)
__device__ uint16_t g_xcp_h [CML * CDIN],  g_xcp_l [CML * CDIN];
__device__ uint16_t g_xdp_h [CML * CXD],   g_xdp_l [CML * CXD];
__device__ uint16_t g_ygp_h [CML * CDIN],  g_ygp_l [CML * CDIN];

// ---------------- helpers ----------------
__device__ __forceinline__ void split_bf16(float x, uint16_t& h, uint16_t& l)
{
    __nv_bfloat16 bh = __float2bfloat16_rn(x);
    float r = x - __bfloat162float(bh);
    __nv_bfloat16 bl = __float2bfloat16_rn(r);
    h = __bfloat16_as_ushort(bh);
    l = __bfloat16_as_ushort(bl);
}

__device__ __forceinline__ void mma_bf16(float* acc, const uint32_t* a, const uint32_t* b)
{
    asm volatile(
        "mma.sync.aligned.m16n8k16.row.col.f32.bf16.bf16.f32 "
        "{%0,%1,%2,%3}, {%4,%5,%6,%7}, {%8,%9}, {%0,%1,%2,%3};\n"
        : "+f"(acc[0]), "+f"(acc[1]), "+f"(acc[2]), "+f"(acc[3])
        : "r"(a[0]), "r"(a[1]), "r"(a[2]), "r"(a[3]), "r"(b[0]), "r"(b[1]));
}

__device__ __forceinline__ void cp_async16(void* smem_ptr, const void* gptr)
{
    uint32_t s = (uint32_t)__cvta_generic_to_shared(smem_ptr);
    asm volatile("cp.async.cg.shared.global [%0], [%1], 16;\n" :: "r"(s), "l"(gptr));
}

// ---------------- pack x (row-major, K contiguous) ----------------
__global__ void pack_x_kernel(const float* __restrict__ x)
{
    int i = blockIdx.x * blockDim.x + threadIdx.x;  // over CML*CD/2
    if (i >= CML * (CD/2)) return;
    float v0 = x[2*i], v1 = x[2*i + 1];
    uint16_t h0, l0, h1, l1;
    split_bf16(v0, h0, l0);
    split_bf16(v1, h1, l1);
    g_xp_h[i] = (uint32_t)h0 | ((uint32_t)h1 << 16);
    g_xp_l[i] = (uint32_t)l0 | ((uint32_t)l1 << 16);
}

// ---------------- transpose-pack weight: W[K][N] -> Wp[N][K/2] u32 ----------------
// grid: (K/64, N/32), block 256
__global__ void pack_w_kernel(const float* __restrict__ W, int K, int N,
                              uint32_t* __restrict__ oh, uint32_t* __restrict__ ol)
{
    __shared__ float sm[64][33];
    int k0 = blockIdx.x * 64;
    int n0 = blockIdx.y * 32;
    int t  = threadIdx.x;
    int c  = t & 31;
    int r0 = t >> 5;    // 0..7
    #pragma unroll
    for (int it = 0; it < 8; it++) {
        int r = r0 + it * 8;
        sm[r][c] = W[(size_t)(k0 + r) * N + n0 + c];
    }
    __syncthreads();
    int k2 = t & 31;     // 0..31
    int nn0 = t >> 5;    // 0..7
    #pragma unroll
    for (int it = 0; it < 4; it++) {
        int n = nn0 + it * 8;
        float v0 = sm[2*k2    ][n];
        float v1 = sm[2*k2 + 1][n];
        uint16_t h0, l0, h1, l1;
        split_bf16(v0, h0, l0);
        split_bf16(v1, h1, l1);
        size_t o = (size_t)(n0 + n) * (K/2) + k0/2 + k2;
        oh[o] = (uint32_t)h0 | ((uint32_t)h1 << 16);
        ol[o] = (uint32_t)l0 | ((uint32_t)l1 << 16);
    }
}

// ---------------- bf16-split tensor-core GEMM ----------------
// C[M,N] = A[M,K] @ B[K,N]; A packed [M][K/2] u32, B packed-transposed [N][K/2] u32.
// BM=BN=128, BK=16 (8 u32 pairs), 256 thr = 8 warps (2x4), warp tile 64x32.
// EPI: 0 plain fp32, 1 softplus(acc+bias[col]), 2 fp32 + bf16 hi/lo split stores.
constexpr int BM = 128, BN = 128;
constexpr int STR = 12;                       // u32 stride (conflict-free frags)
constexpr int PLANE = 128 * STR;              // 1536 u32
constexpr int STAGE_U = 4 * PLANE;            // Ah, Al, Bh, Bl
constexpr int GEMM_SMEM = 2 * STAGE_U * 4;    // 49152 bytes

template<int EPI>
__global__ __launch_bounds__(256, 2)
void tgemm3(int M, int N,
            const uint32_t* __restrict__ Ah_g, const uint32_t* __restrict__ Al_g, int lda2,
            const uint32_t* __restrict__ Bh_g, const uint32_t* __restrict__ Bl_g, int ldb2,
            float* __restrict__ C, uint16_t* __restrict__ Ch, uint16_t* __restrict__ Cl,
            int ldc, const float* __restrict__ bias,
            int k2_begin, int ntiles, int zstride)
{
    extern __shared__ uint32_t sm[];

    const int tid  = threadIdx.x;
    const int warp = tid >> 5;
    const int lane = tid & 31;
    const int g    = lane >> 2;
    const int tg   = lane & 3;

    const int row0 = blockIdx.y * BM;
    const int col0 = blockIdx.x * BN;
    const int wm0  = (warp >> 2) * 64;
    const int wn0  = (warp & 3) * 32;

    const int ldRow   = tid >> 1;      // 0..127
    const int ldPlane = tid & 1;       // 0: hi, 1: lo

    const int k2b = k2_begin + blockIdx.z * zstride;

    float acc[4][4][4];
    #pragma unroll
    for (int i = 0; i < 4; i++)
        #pragma unroll
        for (int j = 0; j < 4; j++)
            #pragma unroll
            for (int r = 0; r < 4; r++) acc[i][j][r] = 0.f;

    // zero OOB B rows (stale-proof; written once, stays zero)
    if (N < BN) {
        for (int idx = tid; idx < (BN - N) * 8 * 2 * 2; idx += 256) {
            int w   = idx & 7;
            int rr  = (idx >> 3) % (BN - N);
            int pl  = (idx >> 3) / (BN - N) & 1;
            int stg = idx >> 4 >= (BN - N) * 2 ? 1 : 0;  // crude but covers both stages
            // recompute cleanly:
            int lin = idx;
            int wq  = lin & 7; lin >>= 3;
            int rq  = lin % (BN - N); lin /= (BN - N);
            int pq  = lin & 1; lin >>= 1;
            int sq  = lin;
            (void)w; (void)rr; (void)pl; (void)stg;
            sm[sq * STAGE_U + (2 + pq) * PLANE + (N + rq) * STR + wq] = 0;
        }
    }
    __syncthreads();

    auto load_stage = [&](int stg, int kt) {
        uint32_t* base = sm + stg * STAGE_U;
        uint32_t* Adst = base + ldPlane * PLANE;            // Ah or Al
        uint32_t* Bdst = base + (2 + ldPlane) * PLANE;      // Bh or Bl
        const uint32_t* Asrc = ldPlane ? Al_g : Ah_g;
        const uint32_t* Bsrc = ldPlane ? Bl_g : Bh_g;

        const size_t aoff = (size_t)(row0 + ldRow) * lda2 + (k2b + kt * 8);
        cp_async16(&Adst[ldRow * STR    ], Asrc + aoff);
        cp_async16(&Adst[ldRow * STR + 4], Asrc + aoff + 4);

        if (col0 + ldRow < N) {
            const size_t boff = (size_t)(col0 + ldRow) * ldb2 + (k2b + kt * 8);
            cp_async16(&Bdst[ldRow * STR    ], Bsrc + boff);
            cp_async16(&Bdst[ldRow * STR + 4], Bsrc + boff + 4);
        }
    };

    load_stage(0, 0);
    asm volatile("cp.async.commit_group;\n" ::: "memory");

    int stg = 0;
    for (int kt = 0; kt < ntiles; kt++) {
        if (kt + 1 < ntiles) {
            load_stage(stg ^ 1, kt + 1);
            asm volatile("cp.async.commit_group;\n" ::: "memory");
            asm volatile("cp.async.wait_group 1;\n" ::: "memory");
        } else {
            asm volatile("cp.async.wait_group 0;\n" ::: "memory");
        }
        __syncthreads();

        const uint32_t* Ah = sm + stg * STAGE_U;
        const uint32_t* Al = Ah + PLANE;
        const uint32_t* Bh = Ah + 2 * PLANE;
        const uint32_t* Bl = Ah + 3 * PLANE;

        uint32_t afh[4][4], afl[4][4];
        #pragma unroll
        for (int mt = 0; mt < 4; mt++) {
            int r = wm0 + mt * 16 + g;
            afh[mt][0] = Ah[ r      * STR + tg    ];
            afh[mt][1] = Ah[(r + 8) * STR + tg    ];
            afh[mt][2] = Ah[ r      * STR + tg + 4];
            afh[mt][3] = Ah[(r + 8) * STR + tg + 4];
            afl[mt][0] = Al[ r      * STR + tg    ];
            afl[mt][1] = Al[(r + 8) * STR + tg    ];
            afl[mt][2] = Al[ r      * STR + tg + 4];
            afl[mt][3] = Al[(r + 8) * STR + tg + 4];
        }
        uint32_t bfh[4][2], bfl[4][2];
        #pragma unroll
        for (int nt = 0; nt < 4; nt++) {
            int c = wn0 + nt * 8 + g;
            bfh[nt][0] = Bh[c * STR + tg    ];
            bfh[nt][1] = Bh[c * STR + tg + 4];
            bfl[nt][0] = Bl[c * STR + tg    ];
            bfl[nt][1] = Bl[c * STR + tg + 4];
        }
        #pragma unroll
        for (int mt = 0; mt < 4; mt++)
            #pragma unroll
            for (int nt = 0; nt < 4; nt++) {
                mma_bf16(acc[mt][nt], afh[mt], bfh[nt]);
                mma_bf16(acc[mt][nt], afh[mt], bfl[nt]);
                mma_bf16(acc[mt][nt], afl[mt], bfh[nt]);
            }
        __syncthreads();
        stg ^= 1;
    }

    float* Cz = C + (size_t)blockIdx.z * CML * ldc;   // split-K partial plane (z=0 otherwise)

    #pragma unroll
    for (int mt = 0; mt < 4; mt++) {
        int r0 = row0 + wm0 + mt * 16 + g;
        #pragma unroll
        for (int nt = 0; nt < 4; nt++) {
            int c0 = col0 + wn0 + nt * 8 + 2 * tg;
            #pragma unroll
            for (int rr = 0; rr < 2; rr++) {
                int r = r0 + rr * 8;
                #pragma unroll
                for (int cc = 0; cc < 2; cc++) {
                    int c = c0 + cc;
                    if (c < N) {
                        float v = acc[mt][nt][rr * 2 + cc];
                        if (EPI == 1) {
                            v = v + bias[c];
                            v = (v > 20.f) ? v : log1pf(__expf(v));
                        }
                        Cz[(size_t)r * ldc + c] = v;
                        if (EPI == 2) {
                            uint16_t h, l;
                            split_bf16(v, h, l);
                            Ch[(size_t)r * ldc + c] = h;
                            Cl[(size_t)r * ldc + c] = l;
                        }
                    }
                }
            }
        }
    }
}

// ---------------- split-K reduce for G2 -> xdbl fp32 + bf16 planes ----------------
__global__ void reduce_xdbl_kernel()
{
    int i = blockIdx.x * blockDim.x + threadIdx.x;
    if (i >= CML * CXD) return;
    float s = 0.f;
    #pragma unroll
    for (int z = 0; z < KSPL; z++) s += g_part[(size_t)z * CML * CXD + i];
    g_xdbl[i] = s;
    uint16_t h, l;
    split_bf16(s, h, l);
    g_xdp_h[i] = h;
    g_xdp_l[i] = l;
}

// ---------------- causal depthwise conv (K=4) + SiLU + bf16 split ----------------
__global__ void conv_silu_kernel(const float* __restrict__ conv_w,
                                 const float* __restrict__ conv_b)
{
    int i = blockIdx.x * blockDim.x + threadIdx.x;
    if (i >= CML * CDIN) return;
    int d  = i & (CDIN - 1);
    int bl = i >> 11;
    int l  = bl & (CL - 1);
    int b  = bl >> 10;

    float acc = conv_b[d];
    #pragma unroll
    for (int k = 0; k < CK; k++) {
        int ll = l - (CK - 1) + k;
        if (ll >= 0) {
            float xin = g_xz[(size_t)(b * CL + ll) * (2 * CDIN) + d];
            acc = fmaf(xin, conv_w[d * CK + k], acc);
        }
    }
    float sig = 1.f / (1.f + __expf(-acc));
    float v = acc * sig;
    g_xc[i] = v;
    uint16_t h, l2;
    split_bf16(v, h, l2);
    g_xcp_h[i] = h;
    g_xcp_l[i] = l2;
}

// ---------------- selective scan (+ skip + gate + bf16 split epi) ----------------
__global__ __launch_bounds__(128)
void scan_kernel(const float* __restrict__ A_log,
                 const float* __restrict__ D_skip)
{
    int warp = (blockIdx.x * blockDim.x + threadIdx.x) >> 5;
    int lane = threadIdx.x & 31;
    int half = lane >> 4;
    int n    = lane & 15;

    int b = warp >> 10;
    int d = ((warp & 1023) << 1) + half;

    float a_coef = -expf(A_log[d * CN + n]);
    float d_skip = D_skip[d];
    float h = 0.f;

    const size_t bl0 = (size_t)b * CL;
    for (int t = 0; t < CL; t++) {
        size_t bl = bl0 + t;
        float dv = g_delta[bl * CDIN + d];
        float xc = g_xc   [bl * CDIN + d];
        float Bn = g_xdbl [bl * CXD + CR + n];
        float Cn = g_xdbl [bl * CXD + CR + CN + n];

        float dA = __expf(dv * a_coef);
        h = fmaf(dA, h, dv * Bn * xc);

        float v = h * Cn;
        v += __shfl_xor_sync(0xffffffffu, v, 8);
        v += __shfl_xor_sync(0xffffffffu, v, 4);
        v += __shfl_xor_sync(0xffffffffu, v, 2);
        v += __shfl_xor_sync(0xffffffffu, v, 1);

        if (n == 0) {
            float zv = g_xz[bl * (2 * CDIN) + CDIN + d];
            float yv = v + xc * d_skip;
            float sig = 1.f / (1.f + __expf(-zv));
            float yg = yv * (zv * sig);
            uint16_t hh, ll;
            split_bf16(yg, hh, ll);
            g_ygp_h[bl * CDIN + d] = hh;
            g_ygp_l[bl * CDIN + d] = ll;
        }
    }
}

// ---------------- LayerNorm over last dim (1024) ----------------
__global__ __launch_bounds__(256)
void ln_kernel(const float* __restrict__ gamma,
               const float* __restrict__ beta,
               float* __restrict__ out)
{
    int row = blockIdx.x;
    const float* p = g_pre + (size_t)row * CD;
    int tid = threadIdx.x;

    float s = 0.f, s2 = 0.f;
    for (int c = tid; c < CD; c += 256) {
        float v = p[c];
        s  += v;
        s2 += v * v;
    }
    #pragma unroll
    for (int o = 16; o >= 1; o >>= 1) {
        s  += __shfl_xor_sync(0xffffffffu, s,  o);
        s2 += __shfl_xor_sync(0xffffffffu, s2, o);
    }
    __shared__ float shs[8], shs2[8];
    int wid = tid >> 5;
    if ((tid & 31) == 0) { shs[wid] = s; shs2[wid] = s2; }
    __syncthreads();
    if (tid < 32) {
        s  = (tid < 8) ? shs[tid]  : 0.f;
        s2 = (tid < 8) ? shs2[tid] : 0.f;
        #pragma unroll
        for (int o = 4; o >= 1; o >>= 1) {
            s  += __shfl_xor_sync(0xffffffffu, s,  o);
            s2 += __shfl_xor_sync(0xffffffffu, s2, o);
        }
        if (tid == 0) { shs[0] = s; shs2[0] = s2; }
    }
    __syncthreads();
    float mean = shs[0] * (1.f / CD);
    float var  = shs2[0] * (1.f / CD) - mean * mean;
    float rstd = rsqrtf(var + CLN_EPS);

    for (int c = tid; c < CD; c += 256) {
        float v = p[c];
        out[(size_t)row * CD + c] = (v - mean) * rstd * gamma[c] + beta[c];
    }
}

// ---------------- launch ----------------
extern "C" void kernel_launch(void* const* d_in, const int* in_sizes, int n_in,
                              void* d_out, int out_size)
{
    const float* x      = (const float*)d_in[0];
    const float* W_in   = (const float*)d_in[1];
    const float* conv_w = (const float*)d_in[2];
    const float* conv_b = (const float*)d_in[3];
    const float* W_x    = (const float*)d_in[4];
    const float* W_dt   = (const float*)d_in[5];
    const float* b_dt   = (const float*)d_in[6];
    const float* A_log  = (const float*)d_in[7];
    const float* D_skip = (const float*)d_in[8];
    const float* W_out  = (const float*)d_in[9];
    const float* ln_g   = (const float*)d_in[10];
    const float* ln_b   = (const float*)d_in[11];
    float* out = (float*)d_out;

    cudaFuncSetAttribute(tgemm3<0>, cudaFuncAttributeMaxDynamicSharedMemorySize, GEMM_SMEM);
    cudaFuncSetAttribute(tgemm3<1>, cudaFuncAttributeMaxDynamicSharedMemorySize, GEMM_SMEM);
    cudaFuncSetAttribute(tgemm3<2>, cudaFuncAttributeMaxDynamicSharedMemorySize, GEMM_SMEM);

    float *p_xz, *p_delta, *p_pre, *p_part;
    uint32_t *p_xph, *p_xpl, *p_Winh, *p_Winl, *p_Wxh, *p_Wxl, *p_Wdth, *p_Wdtl, *p_Wouth, *p_Woutl;
    uint16_t *p_xch, *p_xcl, *p_xdh, *p_xdl, *p_ygh, *p_ygl;
    cudaGetSymbolAddress((void**)&p_xz,    g_xz);
    cudaGetSymbolAddress((void**)&p_delta, g_delta);
    cudaGetSymbolAddress((void**)&p_pre,   g_pre);
    cudaGetSymbolAddress((void**)&p_part,  g_part);
    cudaGetSymbolAddress((void**)&p_xph,   g_xp_h);
    cudaGetSymbolAddress((void**)&p_xpl,   g_xp_l);
    cudaGetSymbolAddress((void**)&p_Winh,  g_Winp_h);
    cudaGetSymbolAddress((void**)&p_Winl,  g_Winp_l);
    cudaGetSymbolAddress((void**)&p_Wxh,   g_Wxp_h);
    cudaGetSymbolAddress((void**)&p_Wxl,   g_Wxp_l);
    cudaGetSymbolAddress((void**)&p_Wdth,  g_Wdtp_h);
    cudaGetSymbolAddress((void**)&p_Wdtl,  g_Wdtp_l);
    cudaGetSymbolAddress((void**)&p_Wouth, g_Woutp_h);
    cudaGetSymbolAddress((void**)&p_Woutl, g_Woutp_l);
    cudaGetSymbolAddress((void**)&p_xch,   g_xcp_h);
    cudaGetSymbolAddress((void**)&p_xcl,   g_xcp_l);
    cudaGetSymbolAddress((void**)&p_xdh,   g_xdp_h);
    cudaGetSymbolAddress((void**)&p_xdl,   g_xdp_l);
    cudaGetSymbolAddress((void**)&p_ygh,   g_ygp_h);
    cudaGetSymbolAddress((void**)&p_ygl,   g_ygp_l);

    // pack inputs/weights
    pack_x_kernel<<<(CML*(CD/2) + 255)/256, 256>>>(x);
    pack_w_kernel<<<dim3(CD/64,   (2*CDIN)/32), 256>>>(W_in,  CD,   2*CDIN, p_Winh,  p_Winl);
    pack_w_kernel<<<dim3(CDIN/64, CXD/32),      256>>>(W_x,   CDIN, CXD,    p_Wxh,   p_Wxl);
    pack_w_kernel<<<dim3(CR/64,   CDIN/32),     256>>>(W_dt,  CR,   CDIN,   p_Wdth,  p_Wdtl);
    pack_w_kernel<<<dim3(CDIN/64, CD/32),       256>>>(W_out, CDIN, CD,     p_Wouth, p_Woutl);

    dim3 thr(256);

    // G1: xz = x @ W_in   [2048x1024]x[1024x4096]
    tgemm3<0><<<dim3((2*CDIN)/128, CML/128), thr, GEMM_SMEM>>>(
        CML, 2*CDIN, p_xph, p_xpl, CD/2, p_Winh, p_Winl, CD/2,
        p_xz, nullptr, nullptr, 2*CDIN, nullptr, 0, (CD/2)/8, 0);

    // conv + silu (+ pack)
    conv_silu_kernel<<<(CML*CDIN + 255)/256, 256>>>(conv_w, conv_b);

    // G2: split-K partials: x_conv @ W_x   [2048x2048]x[2048x96], K chunks of 256
    tgemm3<0><<<dim3(1, CML/128, KSPL), thr, GEMM_SMEM>>>(
        CML, CXD, p_xch ? (const uint32_t*)p_xch : nullptr, (const uint32_t*)p_xcl, CDIN/2,
        p_Wxh, p_Wxl, CDIN/2,
        p_part, nullptr, nullptr, CXD, nullptr, 0, (CDIN/2/KSPL)/8, CDIN/2/KSPL);

    // reduce partials -> xdbl (+ pack)
    reduce_xdbl_kernel<<<(CML*CXD + 255)/256, 256>>>();

    // G3: delta = softplus(dt @ W_dt + b_dt)   [2048x64]x[64x2048]
    tgemm3<1><<<dim3(CDIN/128, CML/128), thr, GEMM_SMEM>>>(
        CML, CDIN, (const uint32_t*)p_xdh, (const uint32_t*)p_xdl, CXD/2,
        p_Wdth, p_Wdtl, CR/2,
        p_delta, nullptr, nullptr, CDIN, b_dt, 0, (CR/2)/8, 0);

    // scan (+ skip + gate + pack)
    scan_kernel<<<(CB*CDIN/2)*32/128, 128>>>(A_log, D_skip);

    // G4: pre = yg @ W_out   [2048x2048]x[2048x1024]
    tgemm3<0><<<dim3(CD/128, CML/128), thr, GEMM_SMEM>>>(
        CML, CD, (const uint32_t*)p_ygh, (const uint32_t*)p_ygl, CDIN/2,
        p_Wouth, p_Woutl, CDIN/2,
        p_pre, nullptr, nullptr, CD, nullptr, 0, (CDIN/2)/8, 0);

    // LayerNorm
    ln_kernel<<<CML, 256>>>(ln_g, ln_b, out);
}